// round 1
// baseline (speedup 1.0000x reference)
#include <cuda_runtime.h>
#include <cstdint>

// Problem constants (fixed by the dataset: B=32, H=W=56, C=384, heads=12, ws=7, shift=3)
#define HEADS   12
#define EMBED   384
#define WS      7
#define NTOK    49            // 7*7 tokens per window
#define NWIN    2048          // 32 batches * 8*8 windows
#define M_TOTAL (NWIN * NTOK) // 100352 rows
#define N_QKV   1152
#define N_PROJ  384

// Scratch (static __device__ arrays: the sanctioned allocation-free workaround)
__device__ float g_qkv[(size_t)M_TOTAL * N_QKV];   // 462 MB: [win*49+t][1152]
__device__ float g_attn[(size_t)M_TOTAL * N_PROJ]; // 154 MB: [win*49+t][384]

// ---------------------------------------------------------------------------
// Window <-> pixel mapping. Shifted image xs[h,w] = x[(h+3)%56,(w+3)%56];
// output scatter uses the SAME map: out[(h+3)%56,(w+3)%56] = out_s[h,w].
// m = win*49 + t, win = b*64 + wh*8 + ww, t = r*7 + c.
__device__ __forceinline__ int win_src_index(int m) {
    int win = m / NTOK, t = m - win * NTOK;
    int b  = win >> 6, wi = win & 63;
    int wh = wi >> 3,  ww = wi & 7;
    int r  = t / WS,   c  = t - r * WS;
    int row = wh * WS + r + 3; if (row >= 56) row -= 56;
    int col = ww * WS + c + 3; if (col >= 56) col -= 56;
    return b * 3136 + row * 56 + col;
}

// ---------------------------------------------------------------------------
// Packed f32x2 helpers (Blackwell FFMA2 — PTX-only path)
__device__ __forceinline__ unsigned long long pack2(float lo, float hi) {
    unsigned long long u;
    asm("mov.b64 %0, {%1, %2};" : "=l"(u) : "f"(lo), "f"(hi));
    return u;
}
__device__ __forceinline__ void unpack2(unsigned long long u, float& lo, float& hi) {
    asm("mov.b64 {%0, %1}, %2;" : "=f"(lo), "=f"(hi) : "l"(u));
}
__device__ __forceinline__ void ffma2(unsigned long long& d,
                                      unsigned long long a,
                                      unsigned long long b) {
    asm("fma.rn.f32x2 %0, %1, %2, %3;" : "=l"(d) : "l"(a), "l"(b), "l"(d));
}

// ---------------------------------------------------------------------------
// Tiled fp32 GEMM, block tile 64(M) x 128(N), K-tile 16, 256 threads,
// per-thread microtile 4(M) x 8(N) computed as 4x4 FFMA2.
// GATHER:  A rows gathered through win_src_index from x (K=384).
// SCATTER: C rows scattered through win_src_index into d_out.
template <int N_TOTAL, bool GATHER, bool SCATTER>
__global__ void __launch_bounds__(256)
gemm_kernel(const float* __restrict__ A,
            const float* __restrict__ B,
            const float* __restrict__ bias,
            float* __restrict__ C)
{
    __shared__ float As[16][65];    // transposed A tile, padded
    __shared__ float Bs[16][128];

    const int tid = threadIdx.x;
    const int tx  = tid & 15;       // N direction (8 cols each)
    const int ty  = tid >> 4;       // M direction (4 rows each)
    const int m0  = blockIdx.y * 64;
    const int n0  = blockIdx.x * 128;

    // A load lanes: 64 rows x 16 k, 4 floats per thread
    const int lm = tid >> 2;            // 0..63
    const int lk = (tid & 3) * 4;       // 0,4,8,12
    const int am = m0 + lm;
    const float* arow;
    if (GATHER) arow = A + (size_t)win_src_index(am) * 384;
    else        arow = A + (size_t)am * 384;

    // B load lanes: 16 k x 128 n, 8 floats per thread
    const int bk = tid >> 4;            // 0..15
    const int bn = (tid & 15) * 8;
    const float* brow = B + (size_t)bk * N_TOTAL + n0 + bn;

    unsigned long long acc[4][4];
#pragma unroll
    for (int i = 0; i < 4; i++)
#pragma unroll
        for (int j = 0; j < 4; j++) acc[i][j] = 0ull;

    for (int k0 = 0; k0 < 384; k0 += 16) {
        float4 av = *reinterpret_cast<const float4*>(arow + k0 + lk);
        As[lk + 0][lm] = av.x;
        As[lk + 1][lm] = av.y;
        As[lk + 2][lm] = av.z;
        As[lk + 3][lm] = av.w;

        const float* bp = brow + (size_t)k0 * N_TOTAL;
        float4 b0 = *reinterpret_cast<const float4*>(bp);
        float4 b1 = *reinterpret_cast<const float4*>(bp + 4);
        *reinterpret_cast<float4*>(&Bs[bk][bn])     = b0;
        *reinterpret_cast<float4*>(&Bs[bk][bn + 4]) = b1;
        __syncthreads();

#pragma unroll
        for (int k = 0; k < 16; k++) {
            float4 bb0 = *reinterpret_cast<const float4*>(&Bs[k][tx * 8]);
            float4 bb1 = *reinterpret_cast<const float4*>(&Bs[k][tx * 8 + 4]);
            unsigned long long bf[4];
            bf[0] = pack2(bb0.x, bb0.y);
            bf[1] = pack2(bb0.z, bb0.w);
            bf[2] = pack2(bb1.x, bb1.y);
            bf[3] = pack2(bb1.z, bb1.w);
#pragma unroll
            for (int i = 0; i < 4; i++) {
                float a = As[k][ty * 4 + i];
                unsigned long long aa = pack2(a, a);
#pragma unroll
                for (int j = 0; j < 4; j++) ffma2(acc[i][j], aa, bf[j]);
            }
        }
        __syncthreads();
    }

    // Epilogue: add bias, write (optionally scattered)
    float bv[8];
    {
        float4 q0 = *reinterpret_cast<const float4*>(bias + n0 + tx * 8);
        float4 q1 = *reinterpret_cast<const float4*>(bias + n0 + tx * 8 + 4);
        bv[0] = q0.x; bv[1] = q0.y; bv[2] = q0.z; bv[3] = q0.w;
        bv[4] = q1.x; bv[5] = q1.y; bv[6] = q1.z; bv[7] = q1.w;
    }
#pragma unroll
    for (int i = 0; i < 4; i++) {
        int m = m0 + ty * 4 + i;
        float* crow;
        if (SCATTER) crow = C + (size_t)win_src_index(m) * N_TOTAL + n0 + tx * 8;
        else         crow = C + (size_t)m * N_TOTAL + n0 + tx * 8;
        float o[8];
#pragma unroll
        for (int j = 0; j < 4; j++) {
            float lo, hi;
            unpack2(acc[i][j], lo, hi);
            o[2 * j]     = lo + bv[2 * j];
            o[2 * j + 1] = hi + bv[2 * j + 1];
        }
        *reinterpret_cast<float4*>(crow)     = make_float4(o[0], o[1], o[2], o[3]);
        *reinterpret_cast<float4*>(crow + 4) = make_float4(o[4], o[5], o[6], o[7]);
    }
}

// ---------------------------------------------------------------------------
// Per-(window, head) attention: 49x32 Q,K,V -> softmax(QK^T*scale + bias) V
// 64 threads/block; thread i < 49 owns attention row i.
__global__ void __launch_bounds__(64)
attn_kernel(const float* __restrict__ bias_table)
{
    const int blk  = blockIdx.x;
    const int head = blk % HEADS;
    const int win  = blk / HEADS;

    __shared__ float Qs[NTOK * 33];   // padded rows: stride 33
    __shared__ float Ks[NTOK * 32];
    __shared__ float Vs[NTOK * 32];
    __shared__ float Os[NTOK * 33];
    __shared__ float Ss[NTOK * 50];   // scores, padded rows: stride 50

    const int tid = threadIdx.x;
    const float* base = g_qkv + (size_t)win * NTOK * N_QKV + head * 32;

    for (int idx = tid; idx < NTOK * 32; idx += 64) {
        int t = idx >> 5, d = idx & 31;
        const float* p = base + (size_t)t * N_QKV + d;
        Qs[t * 33 + d] = p[0];
        Ks[t * 32 + d] = p[384];
        Vs[t * 32 + d] = p[768];
    }
    __syncthreads();

    if (tid < NTOK) {
        const int i  = tid;
        const int ri = i / WS, ci = i - ri * WS;
        const float scale = 0.17677669529663687f;  // 1/sqrt(32)

        float q[32];
#pragma unroll
        for (int d = 0; d < 32; d++) q[d] = Qs[i * 33 + d];

        float mx = -1e30f;
        for (int j = 0; j < NTOK; j++) {
            float acc = 0.f;
#pragma unroll
            for (int d = 0; d < 32; d++) acc += q[d] * Ks[j * 32 + d];
            int rj = j / WS, cj = j - rj * WS;
            int rel = (ri - rj + 6) * 13 + (ci - cj + 6);
            float b = __ldg(&bias_table[rel * HEADS + head]);
            acc = acc * scale + b;
            Ss[i * 50 + j] = acc;
            mx = fmaxf(mx, acc);
        }

        float sum = 0.f;
        for (int j = 0; j < NTOK; j++) {
            float p = __expf(Ss[i * 50 + j] - mx);
            Ss[i * 50 + j] = p;
            sum += p;
        }
        const float inv = 1.0f / sum;

        float o[32];
#pragma unroll
        for (int d = 0; d < 32; d++) o[d] = 0.f;
        for (int j = 0; j < NTOK; j++) {
            float p = Ss[i * 50 + j] * inv;
#pragma unroll
            for (int d = 0; d < 32; d++) o[d] += p * Vs[j * 32 + d];
        }
#pragma unroll
        for (int d = 0; d < 32; d++) Os[i * 33 + d] = o[d];
    }
    __syncthreads();

    float* outbase = g_attn + (size_t)win * NTOK * N_PROJ + head * 32;
    for (int idx = tid; idx < NTOK * 32; idx += 64) {
        int t = idx >> 5, d = idx & 31;
        outbase[(size_t)t * N_PROJ + d] = Os[t * 33 + d];
    }
}

// ---------------------------------------------------------------------------
extern "C" void kernel_launch(void* const* d_in, const int* in_sizes, int n_in,
                              void* d_out, int out_size)
{
    const float* x          = (const float*)d_in[0];  // [32, 3136, 384]
    const float* qkv_w      = (const float*)d_in[1];  // [384, 1152]
    const float* qkv_b      = (const float*)d_in[2];  // [1152]
    const float* proj_w     = (const float*)d_in[3];  // [384, 384]
    const float* proj_b     = (const float*)d_in[4];  // [384]
    const float* bias_table = (const float*)d_in[5];  // [169, 12]
    float* out = (float*)d_out;                       // [32, 3136, 384]

    float* qkv_ptr;
    float* attn_ptr;
    cudaGetSymbolAddress((void**)&qkv_ptr, g_qkv);
    cudaGetSymbolAddress((void**)&attn_ptr, g_attn);

    // 1) QKV GEMM (windowed gather fused into A loads)
    {
        dim3 grid(N_QKV / 128, M_TOTAL / 64);  // 9 x 1568
        gemm_kernel<N_QKV, true, false><<<grid, 256>>>(x, qkv_w, qkv_b, qkv_ptr);
    }
    // 2) Window attention
    attn_kernel<<<NWIN * HEADS, 64>>>(bias_table);
    // 3) Proj GEMM (inverse roll/window scatter fused into epilogue)
    {
        dim3 grid(N_PROJ / 128, M_TOTAL / 64); // 3 x 1568
        gemm_kernel<N_PROJ, false, true><<<grid, 256>>>(attn_ptr, proj_w, proj_b, out);
    }
}

// round 3
// speedup vs baseline: 2.6749x; 2.6749x over previous
#include <cuda_runtime.h>
#include <cstdint>

// Problem constants (B=32, H=W=56, C=384, heads=12, ws=7, shift=3)
#define HEADS   12
#define WS      7
#define NTOK    49
#define NWIN    2048
#define M_TOTAL (NWIN * NTOK)   // 100352
#define N_QKV   1152
#define N_PROJ  384
#define KDIM    384

// GEMM tiling (classic mma.sync path — tcgen05 is 'a'-gated and unavailable)
#define BM 128
#define BN 128
#define BK 16
#define KSTEPS (KDIM / BK)      // 24
#define APAD 20                 // smem row stride (floats): conflict-free frags
#define STAGE_FLOATS (BM * APAD)
#define AB_STAGE (2 * STAGE_FLOATS)
#define CPAD 66
#define SMEM_BYTES (4 * 64 * CPAD * 4)   // 67584 > 2*AB_STAGE*4 (40960)

// Scratch (__device__ globals: sanctioned allocation-free path)
__device__ float g_qkv[(size_t)M_TOTAL * N_QKV];
__device__ float g_attn[(size_t)M_TOTAL * N_PROJ];
__device__ float g_xr  [(size_t)M_TOTAL * KDIM];
__device__ float g_wtq [(size_t)N_QKV * KDIM];
__device__ float g_wtp [(size_t)N_PROJ * KDIM];

// ---------------------------------------------------------------------------
// roll+window gather map (shift is involution-symmetric): m = win*49 + t
__device__ __forceinline__ int win_src_index(int m) {
    int win = m / NTOK, t = m - win * NTOK;
    int b  = win >> 6, wi = win & 63;
    int wh = wi >> 3,  ww = wi & 7;
    int r  = t / WS,   c  = t - r * WS;
    int row = wh * WS + r + 3; if (row >= 56) row -= 56;
    int col = ww * WS + c + 3; if (col >= 56) col -= 56;
    return b * 3136 + row * 56 + col;
}

__device__ __forceinline__ uint32_t smem_u32(const void* p) {
    uint32_t a;
    asm("{ .reg .u64 t; cvta.to.shared.u64 t, %1; cvt.u32.u64 %0, t; }" : "=r"(a) : "l"(p));
    return a;
}
__device__ __forceinline__ float round_tf32(float v) {
    uint32_t r;
    asm("cvt.rna.tf32.f32 %0, %1;" : "=r"(r) : "f"(v));
    return __uint_as_float(r);
}

#define CP16(dst, src) \
    asm volatile("cp.async.cg.shared.global [%0], [%1], 16;" :: "r"(dst), "l"(src) : "memory")
#define CP_COMMIT() asm volatile("cp.async.commit_group;" ::: "memory")
#define CP_WAIT1()  asm volatile("cp.async.wait_group 1;" ::: "memory")
#define CP_WAIT0()  asm volatile("cp.async.wait_group 0;" ::: "memory")

#define MMA_TF32(c, a, b) \
    asm volatile("mma.sync.aligned.m16n8k8.row.col.f32.tf32.tf32.f32 " \
        "{%0,%1,%2,%3}, {%4,%5,%6,%7}, {%8,%9}, {%0,%1,%2,%3};" \
        : "+f"((c)[0]), "+f"((c)[1]), "+f"((c)[2]), "+f"((c)[3]) \
        : "r"((a)[0]), "r"((a)[1]), "r"((a)[2]), "r"((a)[3]), "r"((b)[0]), "r"((b)[1]))

// ---------------------------------------------------------------------------
// tf32 mma.sync GEMM: CTA 128x128, 4 warps (64x64 each), K staged 16 wide,
// 2-stage cp.async pipeline. GATHER fuses roll/window into A row indices,
// SCATTER fuses inverse roll/window into the epilogue row indices.
template <int N_TOTAL, bool GATHER, bool SCATTER>
__global__ void __launch_bounds__(128)
gemm_mma(const float* __restrict__ A, const float* __restrict__ WT,
         const float* __restrict__ bias, float* __restrict__ C)
{
    extern __shared__ float sm[];
    const uint32_t smb = smem_u32(sm);

    const int tid  = threadIdx.x;
    const int wid  = tid >> 5, lane = tid & 31;
    const int g    = lane >> 2, t = lane & 3;
    const int wm   = wid & 1, wn = wid >> 1;       // warp grid 2(M) x 2(N)
    const int m0   = blockIdx.y * BM, n0 = blockIdx.x * BN;

    // global row pointers (one row per thread for loads)
    const float* arow = A + (size_t)(GATHER ? win_src_index(m0 + tid) : (m0 + tid)) * KDIM;
    const float* brow = WT + (size_t)(n0 + tid) * KDIM;

    const uint32_t a_dst = smb + (uint32_t)tid * APAD * 4;
    const uint32_t b_dst = smb + (uint32_t)(STAGE_FLOATS + tid * APAD) * 4;

    auto load_stage = [&](int s, int kt) {
        const float* ap = arow + kt * BK;
        const float* bp = brow + kt * BK;
        const uint32_t so = (uint32_t)s * AB_STAGE * 4;
#pragma unroll
        for (int seg = 0; seg < 4; seg++) {
            CP16(a_dst + so + seg * 16, ap + seg * 4);
            CP16(b_dst + so + seg * 16, bp + seg * 4);
        }
    };

    float c[4][8][4];
#pragma unroll
    for (int i = 0; i < 4; i++)
#pragma unroll
        for (int j = 0; j < 8; j++)
#pragma unroll
            for (int q = 0; q < 4; q++) c[i][j][q] = 0.f;

    load_stage(0, 0); CP_COMMIT();
    load_stage(1, 1); CP_COMMIT();

    for (int kt = 0; kt < KSTEPS; kt++) {
        const int s = kt & 1;
        if (kt == KSTEPS - 1) CP_WAIT0(); else CP_WAIT1();
        __syncthreads();

        const uint32_t* AsU = (const uint32_t*)(sm + s * AB_STAGE);
        const uint32_t* BsU = (const uint32_t*)(sm + s * AB_STAGE + STAGE_FLOATS);

#pragma unroll
        for (int ks = 0; ks < 2; ks++) {
            const int ko = ks * 8;
            uint32_t a[4][4];
#pragma unroll
            for (int i = 0; i < 4; i++) {
                const int r0 = (wm * 64 + i * 16 + g) * APAD + ko + t;
                a[i][0] = AsU[r0];
                a[i][1] = AsU[r0 + 8 * APAD];
                a[i][2] = AsU[r0 + 4];
                a[i][3] = AsU[r0 + 8 * APAD + 4];
            }
            uint32_t b[8][2];
#pragma unroll
            for (int j = 0; j < 8; j++) {
                const int nb = (wn * 64 + j * 8 + g) * APAD + ko + t;
                b[j][0] = BsU[nb];
                b[j][1] = BsU[nb + 4];
            }
#pragma unroll
            for (int i = 0; i < 4; i++)
#pragma unroll
                for (int j = 0; j < 8; j++) MMA_TF32(c[i][j], a[i], b[j]);
        }
        __syncthreads();
        if (kt + 2 < KSTEPS) { load_stage(s, kt + 2); CP_COMMIT(); }
    }

    // epilogue: stage warp's 64x64 in smem, then coalesced (scattered) stores
    __syncthreads();
    float* Cw = sm + wid * 64 * CPAD;
#pragma unroll
    for (int i = 0; i < 4; i++)
#pragma unroll
        for (int j = 0; j < 8; j++) {
            const int rr = (i * 16 + g) * CPAD + j * 8 + 2 * t;
            Cw[rr]                = c[i][j][0];
            Cw[rr + 1]            = c[i][j][1];
            Cw[rr + 8 * CPAD]     = c[i][j][2];
            Cw[rr + 8 * CPAD + 1] = c[i][j][3];
        }
    __syncwarp();

    const int ncol = n0 + wn * 64 + lane * 2;
    const float bx = __ldg(&bias[ncol]);
    const float by = __ldg(&bias[ncol + 1]);
#pragma unroll 4
    for (int r = 0; r < 64; r++) {
        const int m = m0 + wm * 64 + r;
        const size_t orow = SCATTER ? (size_t)win_src_index(m) : (size_t)m;
        float2 v = *reinterpret_cast<const float2*>(&Cw[r * CPAD + lane * 2]);
        v.x += bx; v.y += by;
        *reinterpret_cast<float2*>(&C[orow * N_TOTAL + ncol]) = v;
    }
}

// ---------------------------------------------------------------------------
// Preprocessing: transpose W[K][N] -> WT[N][K], rounded to tf32 (rna, unbiased)
__global__ void transpose_round(const float* __restrict__ W, float* __restrict__ WT,
                                int K, int N)
{
    __shared__ float tbuf[32][33];
    const int n0 = blockIdx.x * 32, k0 = blockIdx.y * 32;
    const int tx = threadIdx.x, ty = threadIdx.y;   // 32 x 8
#pragma unroll
    for (int i = 0; i < 4; i++)
        tbuf[ty + 8 * i][tx] = W[(size_t)(k0 + ty + 8 * i) * N + n0 + tx];
    __syncthreads();
#pragma unroll
    for (int i = 0; i < 4; i++)
        WT[(size_t)(n0 + ty + 8 * i) * K + k0 + tx] = round_tf32(tbuf[tx][ty + 8 * i]);
}

__global__ void round_x_kernel(const float4* __restrict__ in, float4* __restrict__ out, int n4)
{
    int i = blockIdx.x * blockDim.x + threadIdx.x;
    if (i < n4) {
        float4 v = in[i];
        v.x = round_tf32(v.x); v.y = round_tf32(v.y);
        v.z = round_tf32(v.z); v.w = round_tf32(v.w);
        out[i] = v;
    }
}

// ---------------------------------------------------------------------------
// Per-(window, head) attention: 49x32 Q,K,V -> softmax(QK^T*scale + bias) V
// float4-vectorized smem traffic; output tf32-rounded for the proj GEMM.
__global__ void __launch_bounds__(64)
attn_kernel(const float* __restrict__ bias_table)
{
    const int blk  = blockIdx.x;
    const int head = blk % HEADS;
    const int win  = blk / HEADS;

    __shared__ float Qs[NTOK * 36];
    __shared__ float Ks[NTOK * 32];
    __shared__ float Vs[NTOK * 32];
    __shared__ float Os[NTOK * 36];
    __shared__ float Ss[NTOK * 50];

    const int tid = threadIdx.x;
    const float* base = g_qkv + (size_t)win * NTOK * N_QKV + head * 32;

    for (int idx = tid; idx < NTOK * 8; idx += 64) {
        int tt = idx >> 3, w = idx & 7;
        const float4* p = reinterpret_cast<const float4*>(base + (size_t)tt * N_QKV) + w;
        reinterpret_cast<float4*>(Qs)[tt * 9 + w] = p[0];
        reinterpret_cast<float4*>(Ks)[tt * 8 + w] = p[96];    // +384 floats
        reinterpret_cast<float4*>(Vs)[tt * 8 + w] = p[192];   // +768 floats
    }
    __syncthreads();

    if (tid < NTOK) {
        const int i  = tid;
        const int ri = i / WS, ci = i - ri * WS;
        const float scale = 0.17677669529663687f;

        float4 q[8];
        const float4* Q4 = reinterpret_cast<const float4*>(Qs);
        const float4* K4 = reinterpret_cast<const float4*>(Ks);
        const float4* V4 = reinterpret_cast<const float4*>(Vs);
#pragma unroll
        for (int w = 0; w < 8; w++) q[w] = Q4[i * 9 + w];

        float mx = -1e30f;
        for (int j = 0; j < NTOK; j++) {
            float acc = 0.f;
#pragma unroll
            for (int w = 0; w < 8; w++) {
                float4 k = K4[j * 8 + w];
                acc += q[w].x * k.x + q[w].y * k.y + q[w].z * k.z + q[w].w * k.w;
            }
            int rj = j / WS, cj = j - rj * WS;
            int rel = (ri - rj + 6) * 13 + (ci - cj + 6);
            acc = acc * scale + __ldg(&bias_table[rel * HEADS + head]);
            Ss[i * 50 + j] = acc;
            mx = fmaxf(mx, acc);
        }
        float sum = 0.f;
        for (int j = 0; j < NTOK; j++) {
            float p = __expf(Ss[i * 50 + j] - mx);
            Ss[i * 50 + j] = p;
            sum += p;
        }
        const float inv = 1.0f / sum;

        float4 o[8];
#pragma unroll
        for (int w = 0; w < 8; w++) o[w] = make_float4(0.f, 0.f, 0.f, 0.f);
        for (int j = 0; j < NTOK; j++) {
            float p = Ss[i * 50 + j] * inv;
#pragma unroll
            for (int w = 0; w < 8; w++) {
                float4 v = V4[j * 8 + w];
                o[w].x += p * v.x; o[w].y += p * v.y;
                o[w].z += p * v.z; o[w].w += p * v.w;
            }
        }
        float4* O4 = reinterpret_cast<float4*>(Os);
#pragma unroll
        for (int w = 0; w < 8; w++) {
            float4 v = o[w];
            v.x = round_tf32(v.x); v.y = round_tf32(v.y);
            v.z = round_tf32(v.z); v.w = round_tf32(v.w);
            O4[i * 9 + w] = v;
        }
    }
    __syncthreads();

    float* outbase = g_attn + (size_t)win * NTOK * N_PROJ + head * 32;
    for (int idx = tid; idx < NTOK * 8; idx += 64) {
        int tt = idx >> 3, w = idx & 7;
        reinterpret_cast<float4*>(outbase + (size_t)tt * N_PROJ)[w] =
            reinterpret_cast<const float4*>(Os)[tt * 9 + w];
    }
}

// ---------------------------------------------------------------------------
extern "C" void kernel_launch(void* const* d_in, const int* in_sizes, int n_in,
                              void* d_out, int out_size)
{
    const float* x          = (const float*)d_in[0];
    const float* qkv_w      = (const float*)d_in[1];
    const float* qkv_b      = (const float*)d_in[2];
    const float* proj_w     = (const float*)d_in[3];
    const float* proj_b     = (const float*)d_in[4];
    const float* bias_table = (const float*)d_in[5];
    float* out = (float*)d_out;

    float *qkv_p, *attn_p, *xr_p, *wtq_p, *wtp_p;
    cudaGetSymbolAddress((void**)&qkv_p,  g_qkv);
    cudaGetSymbolAddress((void**)&attn_p, g_attn);
    cudaGetSymbolAddress((void**)&xr_p,   g_xr);
    cudaGetSymbolAddress((void**)&wtq_p,  g_wtq);
    cudaGetSymbolAddress((void**)&wtp_p,  g_wtp);

    cudaFuncSetAttribute(gemm_mma<N_QKV, true, false>,
                         cudaFuncAttributeMaxDynamicSharedMemorySize, SMEM_BYTES);
    cudaFuncSetAttribute(gemm_mma<N_PROJ, false, true>,
                         cudaFuncAttributeMaxDynamicSharedMemorySize, SMEM_BYTES);

    // 0) preprocessing (tf32 rna rounding; weights transposed to K-major)
    {
        int n4 = M_TOTAL * KDIM / 4;
        round_x_kernel<<<(n4 + 255) / 256, 256>>>((const float4*)x, (float4*)xr_p, n4);
        transpose_round<<<dim3(N_QKV / 32, KDIM / 32), dim3(32, 8)>>>(qkv_w, wtq_p, KDIM, N_QKV);
        transpose_round<<<dim3(N_PROJ / 32, KDIM / 32), dim3(32, 8)>>>(proj_w, wtp_p, KDIM, N_PROJ);
    }
    // 1) QKV GEMM (tf32 mma.sync, fused window/roll gather)
    gemm_mma<N_QKV, true, false><<<dim3(N_QKV / BN, M_TOTAL / BM), 128, SMEM_BYTES>>>(
        xr_p, wtq_p, qkv_b, qkv_p);
    // 2) window attention
    attn_kernel<<<NWIN * HEADS, 64>>>(bias_table);
    // 3) proj GEMM (tf32 mma.sync, fused inverse roll/window scatter)
    gemm_mma<N_PROJ, false, true><<<dim3(N_PROJ / BN, M_TOTAL / BM), 128, SMEM_BYTES>>>(
        attn_p, wtp_p, proj_b, out);
}

// round 4
// speedup vs baseline: 3.0881x; 1.1545x over previous
#include <cuda_runtime.h>
#include <cstdint>

// Problem constants (B=32, H=W=56, C=384, heads=12, ws=7, shift=3)
#define HEADS   12
#define WS      7
#define NTOK    49
#define NWIN    2048
#define M_TOTAL (NWIN * NTOK)   // 100352
#define N_QKV   1152
#define N_PROJ  384
#define KDIM    384

// GEMM tiling: CTA 128x128, 256 threads (8 warps, warp tile 64x32),
// BK=16, 4-stage cp.async ring, single barrier per K-step, reg-direct epilogue.
#define BM 128
#define BN 128
#define BK 16
#define KSTEPS (KDIM / BK)        // 24
#define APAD 20                   // smem row stride (floats): conflict-free frags
#define STAGE_FLOATS (BM * APAD)  // 2560
#define AB_STAGE (2 * STAGE_FLOATS)
#define NSTG 4
#define SMEM_BYTES (NSTG * AB_STAGE * 4)   // 81920

// Scratch (__device__ globals: sanctioned allocation-free path)
__device__ float g_qkv[(size_t)M_TOTAL * N_QKV];
__device__ float g_attn[(size_t)M_TOTAL * N_PROJ];
__device__ float g_xr  [(size_t)M_TOTAL * KDIM];
__device__ float g_wtq [(size_t)N_QKV * KDIM];
__device__ float g_wtp [(size_t)N_PROJ * KDIM];

// ---------------------------------------------------------------------------
// roll+window gather map (shift is involution-symmetric): m = win*49 + t
__device__ __forceinline__ int win_src_index(int m) {
    int win = m / NTOK, t = m - win * NTOK;
    int b  = win >> 6, wi = win & 63;
    int wh = wi >> 3,  ww = wi & 7;
    int r  = t / WS,   c  = t - r * WS;
    int row = wh * WS + r + 3; if (row >= 56) row -= 56;
    int col = ww * WS + c + 3; if (col >= 56) col -= 56;
    return b * 3136 + row * 56 + col;
}

__device__ __forceinline__ uint32_t smem_u32(const void* p) {
    uint32_t a;
    asm("{ .reg .u64 t; cvta.to.shared.u64 t, %1; cvt.u32.u64 %0, t; }" : "=r"(a) : "l"(p));
    return a;
}
__device__ __forceinline__ float round_tf32(float v) {
    uint32_t r;
    asm("cvt.rna.tf32.f32 %0, %1;" : "=r"(r) : "f"(v));
    return __uint_as_float(r);
}

#define CP16(dst, src) \
    asm volatile("cp.async.cg.shared.global [%0], [%1], 16;" :: "r"(dst), "l"(src) : "memory")
#define CP_COMMIT() asm volatile("cp.async.commit_group;" ::: "memory")
#define CP_WAIT2()  asm volatile("cp.async.wait_group 2;" ::: "memory")
#define CP_WAIT1()  asm volatile("cp.async.wait_group 1;" ::: "memory")
#define CP_WAIT0()  asm volatile("cp.async.wait_group 0;" ::: "memory")

#define MMA_TF32(c, a, b) \
    asm volatile("mma.sync.aligned.m16n8k8.row.col.f32.tf32.tf32.f32 " \
        "{%0,%1,%2,%3}, {%4,%5,%6,%7}, {%8,%9}, {%0,%1,%2,%3};" \
        : "+f"((c)[0]), "+f"((c)[1]), "+f"((c)[2]), "+f"((c)[3]) \
        : "r"((a)[0]), "r"((a)[1]), "r"((a)[2]), "r"((a)[3]), "r"((b)[0]), "r"((b)[1]))

// ---------------------------------------------------------------------------
// tf32 mma.sync GEMM. GATHER fuses roll/window into A rows, SCATTER into C rows.
template <int N_TOTAL, bool GATHER, bool SCATTER>
__global__ void __launch_bounds__(256, 2)
gemm_mma(const float* __restrict__ A, const float* __restrict__ WT,
         const float* __restrict__ bias, float* __restrict__ C)
{
    extern __shared__ float sm[];
    const uint32_t smb = smem_u32(sm);

    const int tid  = threadIdx.x;
    const int wid  = tid >> 5, lane = tid & 31;
    const int g    = lane >> 2, t = lane & 3;
    const int wm   = wid & 1, wn = wid >> 1;       // warp grid 2(M) x 4(N)
    const int m0   = blockIdx.y * BM, n0 = blockIdx.x * BN;

    // loads: 2 threads per row, 8 floats (32B = 2x CP16) each
    const int lrow = tid >> 1, lseg = (tid & 1) * 8;
    const float* arow = A + (size_t)(GATHER ? win_src_index(m0 + lrow) : (m0 + lrow)) * KDIM + lseg;
    const float* brow = WT + (size_t)(n0 + lrow) * KDIM + lseg;
    const uint32_t a_dst = smb + ((uint32_t)lrow * APAD + lseg) * 4;
    const uint32_t b_dst = a_dst + STAGE_FLOATS * 4;

    auto load_stage = [&](int s, int kt) {
        const uint32_t so = (uint32_t)s * AB_STAGE * 4;
        const float* ap = arow + kt * BK;
        const float* bp = brow + kt * BK;
        CP16(a_dst + so,      ap);
        CP16(a_dst + so + 16, ap + 4);
        CP16(b_dst + so,      bp);
        CP16(b_dst + so + 16, bp + 4);
    };

    float c[4][4][4];
#pragma unroll
    for (int i = 0; i < 4; i++)
#pragma unroll
        for (int j = 0; j < 4; j++)
#pragma unroll
            for (int q = 0; q < 4; q++) c[i][j][q] = 0.f;

    // prologue: fill NSTG-1 stages
#pragma unroll
    for (int s = 0; s < NSTG - 1; s++) { load_stage(s, s); CP_COMMIT(); }

#pragma unroll 4
    for (int kt = 0; kt < KSTEPS; kt++) {
        const int rem = KSTEPS - 1 - kt;
        if (rem >= 2)      CP_WAIT2();
        else if (rem == 1) CP_WAIT1();
        else               CP_WAIT0();
        __syncthreads();

        // prefetch into the slot consumed last iteration (safe past the barrier)
        if (kt + NSTG - 1 < KSTEPS) { load_stage((kt + NSTG - 1) & 3, kt + NSTG - 1); CP_COMMIT(); }

        const uint32_t* AsU = (const uint32_t*)(sm + (kt & 3) * AB_STAGE);
        const uint32_t* BsU = AsU + STAGE_FLOATS;

#pragma unroll
        for (int ks = 0; ks < 2; ks++) {
            const int ko = ks * 8;
            uint32_t a[4][4];
#pragma unroll
            for (int i = 0; i < 4; i++) {
                const int r0 = (wm * 64 + i * 16 + g) * APAD + ko + t;
                a[i][0] = AsU[r0];
                a[i][1] = AsU[r0 + 8 * APAD];
                a[i][2] = AsU[r0 + 4];
                a[i][3] = AsU[r0 + 8 * APAD + 4];
            }
            uint32_t b[4][2];
#pragma unroll
            for (int j = 0; j < 4; j++) {
                const int nb = (wn * 32 + j * 8 + g) * APAD + ko + t;
                b[j][0] = BsU[nb];
                b[j][1] = BsU[nb + 4];
            }
#pragma unroll
            for (int i = 0; i < 4; i++)
#pragma unroll
                for (int j = 0; j < 4; j++) MMA_TF32(c[i][j], a[i], b[j]);
        }
    }

    // reg-direct epilogue: each 4-lane group stores 32B contiguous (1 sector)
    const int ncolb = n0 + wn * 32;
    float2 bj[4];
#pragma unroll
    for (int j = 0; j < 4; j++)
        bj[j] = *reinterpret_cast<const float2*>(&bias[ncolb + j * 8 + 2 * t]);

#pragma unroll
    for (int i = 0; i < 4; i++) {
        const int mrow = m0 + wm * 64 + i * 16 + g;
        const size_t r0 = SCATTER ? (size_t)win_src_index(mrow)     : (size_t)mrow;
        const size_t r1 = SCATTER ? (size_t)win_src_index(mrow + 8) : (size_t)(mrow + 8);
        float* p0 = C + r0 * N_TOTAL + ncolb + 2 * t;
        float* p1 = C + r1 * N_TOTAL + ncolb + 2 * t;
#pragma unroll
        for (int j = 0; j < 4; j++) {
            *reinterpret_cast<float2*>(p0 + j * 8) =
                make_float2(c[i][j][0] + bj[j].x, c[i][j][1] + bj[j].y);
            *reinterpret_cast<float2*>(p1 + j * 8) =
                make_float2(c[i][j][2] + bj[j].x, c[i][j][3] + bj[j].y);
        }
    }
}

// ---------------------------------------------------------------------------
// Preprocessing: transpose W[K][N] -> WT[N][K], rounded to tf32 (rna, unbiased)
__global__ void transpose_round(const float* __restrict__ W, float* __restrict__ WT,
                                int K, int N)
{
    __shared__ float tbuf[32][33];
    const int n0 = blockIdx.x * 32, k0 = blockIdx.y * 32;
    const int tx = threadIdx.x, ty = threadIdx.y;   // 32 x 8
#pragma unroll
    for (int i = 0; i < 4; i++)
        tbuf[ty + 8 * i][tx] = W[(size_t)(k0 + ty + 8 * i) * N + n0 + tx];
    __syncthreads();
#pragma unroll
    for (int i = 0; i < 4; i++)
        WT[(size_t)(n0 + ty + 8 * i) * K + k0 + tx] = round_tf32(tbuf[tx][ty + 8 * i]);
}

__global__ void round_x_kernel(const float4* __restrict__ in, float4* __restrict__ out, int n4)
{
    int i = blockIdx.x * blockDim.x + threadIdx.x;
    if (i < n4) {
        float4 v = in[i];
        v.x = round_tf32(v.x); v.y = round_tf32(v.y);
        v.z = round_tf32(v.z); v.w = round_tf32(v.w);
        out[i] = v;
    }
}

// ---------------------------------------------------------------------------
// Per-(window, head) attention: 49x32 Q,K,V -> softmax(QK^T*scale + bias) V
__global__ void __launch_bounds__(64)
attn_kernel(const float* __restrict__ bias_table)
{
    const int blk  = blockIdx.x;
    const int head = blk % HEADS;
    const int win  = blk / HEADS;

    __shared__ float Qs[NTOK * 36];
    __shared__ float Ks[NTOK * 32];
    __shared__ float Vs[NTOK * 32];
    __shared__ float Os[NTOK * 36];
    __shared__ float Ss[NTOK * 50];

    const int tid = threadIdx.x;
    const float* base = g_qkv + (size_t)win * NTOK * N_QKV + head * 32;

    for (int idx = tid; idx < NTOK * 8; idx += 64) {
        int tt = idx >> 3, w = idx & 7;
        const float4* p = reinterpret_cast<const float4*>(base + (size_t)tt * N_QKV) + w;
        reinterpret_cast<float4*>(Qs)[tt * 9 + w] = p[0];
        reinterpret_cast<float4*>(Ks)[tt * 8 + w] = p[96];    // +384 floats
        reinterpret_cast<float4*>(Vs)[tt * 8 + w] = p[192];   // +768 floats
    }
    __syncthreads();

    if (tid < NTOK) {
        const int i  = tid;
        const int ri = i / WS, ci = i - ri * WS;
        const float scale = 0.17677669529663687f;

        float4 q[8];
        const float4* Q4 = reinterpret_cast<const float4*>(Qs);
        const float4* K4 = reinterpret_cast<const float4*>(Ks);
        const float4* V4 = reinterpret_cast<const float4*>(Vs);
#pragma unroll
        for (int w = 0; w < 8; w++) q[w] = Q4[i * 9 + w];

        float mx = -1e30f;
        for (int j = 0; j < NTOK; j++) {
            float acc = 0.f;
#pragma unroll
            for (int w = 0; w < 8; w++) {
                float4 k = K4[j * 8 + w];
                acc += q[w].x * k.x + q[w].y * k.y + q[w].z * k.z + q[w].w * k.w;
            }
            int rj = j / WS, cj = j - rj * WS;
            int rel = (ri - rj + 6) * 13 + (ci - cj + 6);
            acc = acc * scale + __ldg(&bias_table[rel * HEADS + head]);
            Ss[i * 50 + j] = acc;
            mx = fmaxf(mx, acc);
        }
        float sum = 0.f;
        for (int j = 0; j < NTOK; j++) {
            float p = __expf(Ss[i * 50 + j] - mx);
            Ss[i * 50 + j] = p;
            sum += p;
        }
        const float inv = 1.0f / sum;

        float4 o[8];
#pragma unroll
        for (int w = 0; w < 8; w++) o[w] = make_float4(0.f, 0.f, 0.f, 0.f);
        for (int j = 0; j < NTOK; j++) {
            float p = Ss[i * 50 + j] * inv;
#pragma unroll
            for (int w = 0; w < 8; w++) {
                float4 v = V4[j * 8 + w];
                o[w].x += p * v.x; o[w].y += p * v.y;
                o[w].z += p * v.z; o[w].w += p * v.w;
            }
        }
        float4* O4 = reinterpret_cast<float4*>(Os);
#pragma unroll
        for (int w = 0; w < 8; w++) {
            float4 v = o[w];
            v.x = round_tf32(v.x); v.y = round_tf32(v.y);
            v.z = round_tf32(v.z); v.w = round_tf32(v.w);
            O4[i * 9 + w] = v;
        }
    }
    __syncthreads();

    float* outbase = g_attn + (size_t)win * NTOK * N_PROJ + head * 32;
    for (int idx = tid; idx < NTOK * 8; idx += 64) {
        int tt = idx >> 3, w = idx & 7;
        reinterpret_cast<float4*>(outbase + (size_t)tt * N_PROJ)[w] =
            reinterpret_cast<const float4*>(Os)[tt * 9 + w];
    }
}

// ---------------------------------------------------------------------------
extern "C" void kernel_launch(void* const* d_in, const int* in_sizes, int n_in,
                              void* d_out, int out_size)
{
    const float* x          = (const float*)d_in[0];
    const float* qkv_w      = (const float*)d_in[1];
    const float* qkv_b      = (const float*)d_in[2];
    const float* proj_w     = (const float*)d_in[3];
    const float* proj_b     = (const float*)d_in[4];
    const float* bias_table = (const float*)d_in[5];
    float* out = (float*)d_out;

    float *qkv_p, *attn_p, *xr_p, *wtq_p, *wtp_p;
    cudaGetSymbolAddress((void**)&qkv_p,  g_qkv);
    cudaGetSymbolAddress((void**)&attn_p, g_attn);
    cudaGetSymbolAddress((void**)&xr_p,   g_xr);
    cudaGetSymbolAddress((void**)&wtq_p,  g_wtq);
    cudaGetSymbolAddress((void**)&wtp_p,  g_wtp);

    cudaFuncSetAttribute(gemm_mma<N_QKV, true, false>,
                         cudaFuncAttributeMaxDynamicSharedMemorySize, SMEM_BYTES);
    cudaFuncSetAttribute(gemm_mma<N_PROJ, false, true>,
                         cudaFuncAttributeMaxDynamicSharedMemorySize, SMEM_BYTES);

    // 0) preprocessing (tf32 rna rounding; weights transposed to K-major)
    {
        int n4 = M_TOTAL * KDIM / 4;
        round_x_kernel<<<(n4 + 255) / 256, 256>>>((const float4*)x, (float4*)xr_p, n4);
        transpose_round<<<dim3(N_QKV / 32, KDIM / 32), dim3(32, 8)>>>(qkv_w, wtq_p, KDIM, N_QKV);
        transpose_round<<<dim3(N_PROJ / 32, KDIM / 32), dim3(32, 8)>>>(proj_w, wtp_p, KDIM, N_PROJ);
    }
    // 1) QKV GEMM (tf32 mma.sync, fused window/roll gather)
    gemm_mma<N_QKV, true, false><<<dim3(N_QKV / BN, M_TOTAL / BM), 256, SMEM_BYTES>>>(
        xr_p, wtq_p, qkv_b, qkv_p);
    // 2) window attention
    attn_kernel<<<NWIN * HEADS, 64>>>(bias_table);
    // 3) proj GEMM (tf32 mma.sync, fused inverse roll/window scatter)
    gemm_mma<N_PROJ, false, true><<<dim3(N_PROJ / BN, M_TOTAL / BM), 256, SMEM_BYTES>>>(
        attn_p, wtp_p, proj_b, out);
}